// round 5
// baseline (speedup 1.0000x reference)
#include <cuda_runtime.h>
#include <math.h>

#define NLEV 3
#define NBMAX 16
#define MAXB 64
#define NCLS 80
// blocks per image-level: ceil(HW/256) -> 52*52=2704:11, 26*26=676:3, 13*13=169:1
#define LB0 11
#define LB1 3
#define LB2 1
#define LBPI (LB0 + LB1 + LB2)   // 15 -> N=16 => 240 blocks

__constant__ float c_stride[NLEV] = {8.f, 16.f, 32.f};
__constant__ float c_anchor[NLEV][3][2] = {
    {{12.f, 16.f}, {19.f, 36.f}, {40.f, 28.f}},
    {{36.f, 75.f}, {76.f, 55.f}, {72.f, 146.f}},
    {{142.f, 110.f}, {192.f, 243.f}, {459.f, 401.f}}
};
__constant__ unsigned c_grpsize[NLEV] = {LB0, LB1, LB2};

// Persistent scratch; statically zero-initialized, and the finalize branch
// resets everything it dirtied so each graph replay starts clean.
__device__ float4   g_boxes[NLEV][NBMAX][MAXB];
__device__ float    g_area [NLEV][NBMAX][MAXB];
__device__ int      g_count[NLEV][NBMAX];
__device__ unsigned g_grp  [NLEV][NBMAX];
__device__ double   g_acc[3];
__device__ unsigned g_done;

__device__ __forceinline__ float bce_logits(float x, float t) {
    return fmaxf(x, 0.f) - x * t + __logf(1.f + __expf(-fabsf(x)));
}

__global__ void __launch_bounds__(256, 2)
k_yolo(const float* __restrict__ f0, const float* __restrict__ f1,
       const float* __restrict__ f2,
       const float* __restrict__ lab0, const float* __restrict__ lab1,
       const float* __restrict__ lab2,
       int N, float* __restrict__ out) {
    // decode (image n, level, chunk)
    const int b = blockIdx.x;
    const int n = b / LBPI;
    const int r = b - n * LBPI;
    int lev, chunk, H;
    const float* feat; const float* label;
    if (r < LB0)            { lev = 0; chunk = r;             H = 52; feat = f0; label = lab0; }
    else if (r < LB0 + LB1) { lev = 1; chunk = r - LB0;       H = 26; feat = f1; label = lab1; }
    else                    { lev = 2; chunk = r - LB0 - LB1; H = 13; feat = f2; label = lab2; }
    const int W = H, HW = H * W;

    const int hw = chunk * 256 + threadIdx.x;   // one grid cell, all 3 anchors
    const bool active = hw < HW;

    // ---- Phase A: issue ALL loads for this cell (MLP ~18), gather positives ----
    float lc[3], rx[3], ry[3], rw[3], rh[3], rc[3];
    const float* Lb = label + (size_t)(n * HW + hw) * 255;        // 3 anchors * 85
    const float* Fb = feat  + (size_t)n * 255 * HW + hw;
    if (active) {
        #pragma unroll
        for (int a = 0; a < 3; a++) lc[a] = __ldg(Lb + a * 85 + 4);
        #pragma unroll
        for (int a = 0; a < 3; a++) {
            const float* fb = Fb + (size_t)(a * 85) * HW;
            rx[a] = fb[0];
            ry[a] = fb[(size_t)HW];
            rw[a] = fb[(size_t)2 * HW];
            rh[a] = fb[(size_t)3 * HW];
            rc[a] = fb[(size_t)4 * HW];
        }
        #pragma unroll
        for (int a = 0; a < 3; a++) {
            if (lc[a] > 0.f) {    // rare (~0.08%)
                const float x = __ldg(Lb + a * 85 + 0);
                const float y = __ldg(Lb + a * 85 + 1);
                const float w = __ldg(Lb + a * 85 + 2);
                const float h = __ldg(Lb + a * 85 + 3);
                const int slot = atomicAdd(&g_count[lev][n], 1);
                if (slot < MAXB) {
                    g_boxes[lev][n][slot] = make_float4(x - 0.5f * w, y - 0.5f * h,
                                                        x + 0.5f * w, y + 0.5f * h);
                    g_area[lev][n][slot] = w * h;
                }
            }
        }
    } else {
        #pragma unroll
        for (int a = 0; a < 3; a++) { lc[a] = rx[a] = ry[a] = rw[a] = rh[a] = rc[a] = 0.f; }
    }

    // ---- per-(lev,image) group barrier (11/3/1 blocks) ----
    __threadfence();
    __syncthreads();
    if (threadIdx.x == 0) {
        const unsigned gs = c_grpsize[lev];
        if (gs > 1u) {
            atomicAdd(&g_grp[lev][n], 1u);
            volatile unsigned* p = &g_grp[lev][n];
            while (*p < gs) { }
            __threadfence();
        }
    }
    __syncthreads();

    // ---- boxes into smem ----
    __shared__ float4 s_box[MAXB];
    __shared__ float  s_area[MAXB];
    const int cnt = min(g_count[lev][n], MAXB);
    if (threadIdx.x < cnt) {
        s_box[threadIdx.x]  = g_boxes[lev][n][threadIdx.x];
        s_area[threadIdx.x] = g_area[lev][n][threadIdx.x];
    }
    __syncthreads();

    // ---- Phase B: loss for 3 anchors ----
    float r_reg = 0.f, r_conf = 0.f, r_prob = 0.f;
    if (active) {
        const float gx = (float)(hw % W);
        const float gy = (float)(hw / W);
        const float stride = c_stride[lev];

        float px1[3], py1[3], px2[3], py2[3], pa[3];
        #pragma unroll
        for (int a = 0; a < 3; a++) {
            const float px = (__fdividef(1.f, 1.f + __expf(-rx[a])) + gx) * stride;
            const float py = (__fdividef(1.f, 1.f + __expf(-ry[a])) + gy) * stride;
            const float pw = __expf(rw[a]) * c_anchor[lev][a][0];
            const float ph = __expf(rh[a]) * c_anchor[lev][a][1];
            px1[a] = px - 0.5f * pw; py1[a] = py - 0.5f * ph;
            px2[a] = px + 0.5f * pw; py2[a] = py + 0.5f * ph;
            pa[a] = pw * ph;
        }

        // ignore = (max_iou < 0.5);  iou<0.5 <=> 2*inter < max(union,1e-9)
        bool ign0 = true, ign1 = true, ign2 = true;
        for (int k = 0; k < cnt; k++) {
            const float4 t = s_box[k];
            const float ar = s_area[k];
            {
                float iw = fmaxf(fminf(px2[0], t.z) - fmaxf(px1[0], t.x), 0.f);
                float ih = fmaxf(fminf(py2[0], t.w) - fmaxf(py1[0], t.y), 0.f);
                float inter = iw * ih;
                if (2.f * inter >= fmaxf(pa[0] + ar - inter, 1e-9f)) ign0 = false;
            }
            {
                float iw = fmaxf(fminf(px2[1], t.z) - fmaxf(px1[1], t.x), 0.f);
                float ih = fmaxf(fminf(py2[1], t.w) - fmaxf(py1[1], t.y), 0.f);
                float inter = iw * ih;
                if (2.f * inter >= fmaxf(pa[1] + ar - inter, 1e-9f)) ign1 = false;
            }
            {
                float iw = fmaxf(fminf(px2[2], t.z) - fmaxf(px1[2], t.x), 0.f);
                float ih = fmaxf(fminf(py2[2], t.w) - fmaxf(py1[2], t.y), 0.f);
                float inter = iw * ih;
                if (2.f * inter >= fmaxf(pa[2] + ar - inter, 1e-9f)) ign2 = false;
            }
        }
        const bool ign[3] = {ign0, ign1, ign2};

        #pragma unroll
        for (int a = 0; a < 3; a++) {
            const bool pos = lc[a] > 0.f;
            const float bc = bce_logits(rc[a], pos ? 1.f : 0.f);
            r_conf += pos ? bc : (ign[a] ? bc : 0.f);

            if (pos) {   // rare path; label sector is L2/L1 hot from phase A
                const float lx = __ldg(Lb + a * 85 + 0);
                const float ly = __ldg(Lb + a * 85 + 1);
                const float lw = __ldg(Lb + a * 85 + 2);
                const float lh = __ldg(Lb + a * 85 + 3);
                const float scale = 2.f - lw * lh * (1.f / (416.f * 416.f));
                const float inv_s = __fdividef(1.f, stride);
                const float ox = lx * inv_s - gx;
                const float oy = ly * inv_s - gy;
                float xy = bce_logits(rx[a], ox) + bce_logits(ry[a], oy);
                const float wx = __logf(__fdividef(lw, c_anchor[lev][a][0]) + 1e-7f);
                const float wy = __logf(__fdividef(lh, c_anchor[lev][a][1]) + 1e-7f);
                const float dwx = rw[a] - wx, dwy = rh[a] - wy;
                r_reg += scale * (xy + 0.5f * (dwx * dwx + dwy * dwy));

                const float* fb = Fb + (size_t)(a * 85) * HW;
                float ps = 0.f;
                #pragma unroll 4
                for (int c = 0; c < NCLS; c++) {
                    float rp = fb[(size_t)(5 + c) * HW];
                    float lp = __ldg(Lb + a * 85 + 5 + c);
                    ps += bce_logits(rp, lp);
                }
                r_prob += ps;
            }
        }
    }

    // ---- block reduction + last-block finalize ----
    #pragma unroll
    for (int o = 16; o; o >>= 1) {
        r_reg  += __shfl_xor_sync(0xffffffffu, r_reg,  o);
        r_conf += __shfl_xor_sync(0xffffffffu, r_conf, o);
        r_prob += __shfl_xor_sync(0xffffffffu, r_prob, o);
    }
    __shared__ float s_r[8], s_c[8], s_p[8];
    const int warp = threadIdx.x >> 5, lane = threadIdx.x & 31;
    if (lane == 0) { s_r[warp] = r_reg; s_c[warp] = r_conf; s_p[warp] = r_prob; }
    __syncthreads();

    if (threadIdx.x == 0) {
        float R = 0.f, C = 0.f, P = 0.f;
        #pragma unroll
        for (int w = 0; w < 8; w++) { R += s_r[w]; C += s_c[w]; P += s_p[w]; }
        atomicAdd(&g_acc[0], (double)R);
        atomicAdd(&g_acc[1], (double)C);
        atomicAdd(&g_acc[2], (double)P);

        __threadfence();
        unsigned t = atomicAdd(&g_done, 1u);
        if (t == (unsigned)gridDim.x - 1u) {
            double v0 = atomicAdd(&g_acc[0], 0.0);
            double v1 = atomicAdd(&g_acc[1], 0.0);
            double v2 = atomicAdd(&g_acc[2], 0.0);
            double invN = 1.0 / (double)N;
            out[0] = (float)(v0 * invN);
            out[1] = (float)(v1 * invN);
            out[2] = (float)(v2 * invN);
            g_acc[0] = 0.0; g_acc[1] = 0.0; g_acc[2] = 0.0;
            #pragma unroll
            for (int l = 0; l < NLEV; l++)
                #pragma unroll
                for (int m = 0; m < NBMAX; m++) { g_count[l][m] = 0; g_grp[l][m] = 0u; }
            g_done = 0u;
            __threadfence();
        }
    }
}

extern "C" void kernel_launch(void* const* d_in, const int* in_sizes, int n_in,
                              void* d_out, int out_size) {
    const float* f0 = (const float*)d_in[0];
    const float* f1 = (const float*)d_in[1];
    const float* f2 = (const float*)d_in[2];
    const float* l0 = (const float*)d_in[3];
    const float* l1 = (const float*)d_in[4];
    const float* l2 = (const float*)d_in[5];

    int N = in_sizes[0] / (255 * 52 * 52);
    if (N > NBMAX) N = NBMAX;

    k_yolo<<<N * LBPI, 256>>>(f0, f1, f2, l0, l1, l2, N, (float*)d_out);
}